// round 4
// baseline (speedup 1.0000x reference)
#include <cuda_runtime.h>
#include <cstdint>

// ---------------------------------------------------------------------------
// BlockwiseToPixels: out[tok] = x[tok] @ W[idx[tok]] + b[idx[tok]]
// B=32, T=8192 -> N=262144 tokens, D=256, P=64, E=16.
//
// Strategy: grid = (token tiles of 4096) x (16 experts). Each CTA:
//   1) loads W[e] (256x64 f32, tf32-rounded) into padded smem,
//   2) compacts matching token ids of its tile into smem,
//   3) chunk loop (64 rows): gather x rows -> smem, tf32 mma.sync GEMM
//      (64x64x256), scatter results with bias.
// Every x row is read exactly once chip-wide; W stays L2/smem resident.
// ---------------------------------------------------------------------------

#define TILE_TOKENS 4096
#define NTHREADS    256
#define D_DIM       256
#define P_DIM       64
#define M_CH        64
#define XS_STRIDE   260   // 256 + 4 pad  -> A-frag loads conflict-free
#define WS_STRIDE   72    // 64 + 8 pad   -> B-frag loads conflict-free

// shared memory layout (float units)
#define WS_OFF      0
#define WS_FLOATS   (D_DIM * WS_STRIDE)        // 18432
#define XS_OFF      (WS_OFF + WS_FLOATS)       // 18432
#define XS_FLOATS   (M_CH * XS_STRIDE)         // 16640
#define BIAS_OFF    (XS_OFF + XS_FLOATS)       // 35072
#define LIST_OFF    (BIAS_OFF + P_DIM)         // 35136
#define CNT_OFF     (LIST_OFF + TILE_TOKENS)   // 39232
#define SMEM_FLOATS (CNT_OFF + 8)              // 39240
#define SMEM_BYTES  (SMEM_FLOATS * 4)          // 156960 bytes

__device__ __forceinline__ float tf32r(float f) {
    uint32_t u;
    asm("cvt.rna.tf32.f32 %0, %1;" : "=r"(u) : "f"(f));
    return __uint_as_float(u);
}

__device__ __forceinline__ void mma8(float c[4],
                                     uint32_t a0, uint32_t a1, uint32_t a2, uint32_t a3,
                                     uint32_t b0, uint32_t b1) {
    asm volatile(
        "mma.sync.aligned.m16n8k8.row.col.f32.tf32.tf32.f32 "
        "{%0,%1,%2,%3}, {%4,%5,%6,%7}, {%8,%9}, {%0,%1,%2,%3};"
        : "+f"(c[0]), "+f"(c[1]), "+f"(c[2]), "+f"(c[3])
        : "r"(a0), "r"(a1), "r"(a2), "r"(a3), "r"(b0), "r"(b1));
}

__global__ void __launch_bounds__(NTHREADS, 1)
moe_pixels_kernel(const float* __restrict__ x,
                  const float* __restrict__ W,
                  const float* __restrict__ bias,
                  const int* __restrict__ bidx,
                  float* __restrict__ out,
                  int n_tok) {
    extern __shared__ float sm[];
    float* Ws   = sm + WS_OFF;
    float* Xs   = sm + XS_OFF;
    float* Bs   = sm + BIAS_OFF;
    int*   list = (int*)(sm + LIST_OFF);
    int*   cnt  = (int*)(sm + CNT_OFF);

    const int tid       = threadIdx.x;
    const int e         = blockIdx.y;
    const int tile_base = blockIdx.x * TILE_TOKENS;

    if (tid == 0) *cnt = 0;
    __syncthreads();

    // ---- load W[e] into padded smem (tf32-rounded) -------------------------
    const float4* Wg = (const float4*)(W + (size_t)e * D_DIM * P_DIM);
    for (int i = tid; i < (D_DIM * P_DIM) / 4; i += NTHREADS) {
        int k  = i >> 4;   // 16 float4 per 64-wide row
        int c4 = i & 15;
        float4 v = Wg[i];
        v.x = tf32r(v.x); v.y = tf32r(v.y); v.z = tf32r(v.z); v.w = tf32r(v.w);
        *(float4*)(Ws + k * WS_STRIDE + c4 * 4) = v;
    }
    if (tid < P_DIM) Bs[tid] = bias[e * P_DIM + tid];

    // ---- compact matching token ids ---------------------------------------
    #pragma unroll
    for (int i = 0; i < TILE_TOKENS / NTHREADS; i++) {
        int pos = tile_base + tid + i * NTHREADS;
        if (pos < n_tok && bidx[pos] == e) {
            int p = atomicAdd(cnt, 1);
            list[p] = pos;
        }
    }
    __syncthreads();
    const int m = *cnt;

    const int warp = tid >> 5;
    const int lane = tid & 31;
    const int g    = lane >> 2;   // 0..7
    const int t    = lane & 3;    // 0..3
    const int wr   = warp >> 1;   // 0..3 : row group (16 rows each)
    const int wc   = warp & 1;    // 0..1 : col group (32 cols each)

    const float4* x4 = (const float4*)x;

    for (int cb = 0; cb < m; cb += M_CH) {
        const int nrows = min(M_CH, m - cb);

        // ---- gather x rows for this chunk (tf32-rounded) ------------------
        for (int i = tid; i < nrows * (D_DIM / 4); i += NTHREADS) {
            int row = i >> 6;       // 64 float4 per row
            int c4  = i & 63;
            int tok = list[cb + row];
            float4 v = x4[(size_t)tok * (D_DIM / 4) + c4];
            v.x = tf32r(v.x); v.y = tf32r(v.y); v.z = tf32r(v.z); v.w = tf32r(v.w);
            *(float4*)(Xs + row * XS_STRIDE + c4 * 4) = v;
        }
        __syncthreads();

        // ---- 64x64x256 tf32 MMA, accumulators seeded with bias ------------
        float c[4][4];
        #pragma unroll
        for (int nt = 0; nt < 4; nt++) {
            int col = wc * 32 + nt * 8 + 2 * t;
            c[nt][0] = Bs[col];
            c[nt][1] = Bs[col + 1];
            c[nt][2] = c[nt][0];
            c[nt][3] = c[nt][1];
        }

        const float* xa = Xs + (wr * 16 + g) * XS_STRIDE;
        #pragma unroll 4
        for (int kk = 0; kk < D_DIM / 8; kk++) {
            const int k0 = kk * 8;
            uint32_t a0 = __float_as_uint(xa[k0 + t]);
            uint32_t a1 = __float_as_uint(xa[8 * XS_STRIDE + k0 + t]);
            uint32_t a2 = __float_as_uint(xa[k0 + t + 4]);
            uint32_t a3 = __float_as_uint(xa[8 * XS_STRIDE + k0 + t + 4]);
            const float* wb = Ws + (k0 + t) * WS_STRIDE + wc * 32 + g;
            #pragma unroll
            for (int nt = 0; nt < 4; nt++) {
                uint32_t b0 = __float_as_uint(wb[nt * 8]);
                uint32_t b1 = __float_as_uint(wb[4 * WS_STRIDE + nt * 8]);
                mma8(c[nt], a0, a1, a2, a3, b0, b1);
            }
        }

        // ---- scatter results ----------------------------------------------
        const int rr0 = cb + wr * 16 + g;
        const int rr1 = rr0 + 8;
        const int tok0 = (rr0 < m) ? list[rr0] : -1;
        const int tok1 = (rr1 < m) ? list[rr1] : -1;
        #pragma unroll
        for (int nt = 0; nt < 4; nt++) {
            int col = wc * 32 + nt * 8 + 2 * t;
            if (tok0 >= 0)
                *(float2*)(out + (size_t)tok0 * P_DIM + col) = make_float2(c[nt][0], c[nt][1]);
            if (tok1 >= 0)
                *(float2*)(out + (size_t)tok1 * P_DIM + col) = make_float2(c[nt][2], c[nt][3]);
        }
        __syncthreads();   // protect Xs before next gather overwrites it
    }
}

extern "C" void kernel_launch(void* const* d_in, const int* in_sizes, int n_in,
                              void* d_out, int out_size) {
    const float* x    = (const float*)d_in[0];   // [B*T, 256] f32
    const float* W    = (const float*)d_in[1];   // [16, 256, 64] f32
    const float* b    = (const float*)d_in[2];   // [16, 64] f32
    const int*   bidx = (const int*)d_in[3];     // [B*T] i32
    float*       out  = (float*)d_out;           // [B*T, 64] f32

    const int n_tok = in_sizes[3];

    cudaFuncSetAttribute(moe_pixels_kernel,
                         cudaFuncAttributeMaxDynamicSharedMemorySize, SMEM_BYTES);

    dim3 grid((n_tok + TILE_TOKENS - 1) / TILE_TOKENS, 16);
    moe_pixels_kernel<<<grid, NTHREADS, SMEM_BYTES>>>(x, W, b, bidx, out, n_tok);
}

// round 8
// speedup vs baseline: 3.1495x; 3.1495x over previous
#include <cuda_runtime.h>
#include <cstdint>

// ---------------------------------------------------------------------------
// BlockwiseToPixels: out[tok] = x[tok] @ W[idx[tok]] + b[idx[tok]]
// B=32, T=8192 -> N=262144 tokens, D=256, P=64, E=16.
//
// R4: cp.async double-buffered gather overlapped with tf32 mma.sync compute,
//     512 threads (16 warps, 16x16 warp tiles), W + 2 X-chunk buffers in smem.
// ---------------------------------------------------------------------------

#define TILE_TOKENS 4096
#define NTHREADS    512
#define D_DIM       256
#define P_DIM       64
#define M_CH        64
#define XS_STRIDE   260   // 256 + 4 pad  -> A-frag LDS conflict-free
#define WS_STRIDE   72    // 64 + 8 pad   -> B-frag LDS conflict-free

// shared memory layout (float units)
#define WS_OFF      0
#define WS_FLOATS   (D_DIM * WS_STRIDE)          // 18432
#define XS_FLOATS   (M_CH * XS_STRIDE)           // 16640
#define XS0_OFF     (WS_OFF + WS_FLOATS)         // 18432
#define XS1_OFF     (XS0_OFF + XS_FLOATS)        // 35072
#define BIAS_OFF    (XS1_OFF + XS_FLOATS)        // 51712
#define LIST_OFF    (BIAS_OFF + P_DIM)           // 51776
#define CNT_OFF     (LIST_OFF + TILE_TOKENS)     // 55872
#define SMEM_FLOATS (CNT_OFF + 8)                // 55880
#define SMEM_BYTES  (SMEM_FLOATS * 4)            // 223520 bytes (< 227KB cap)

__device__ __forceinline__ float tf32r(float f) {
    uint32_t u;
    asm("cvt.rna.tf32.f32 %0, %1;" : "=r"(u) : "f"(f));
    return __uint_as_float(u);
}

__device__ __forceinline__ void mma8(float c[4],
                                     uint32_t a0, uint32_t a1, uint32_t a2, uint32_t a3,
                                     uint32_t b0, uint32_t b1) {
    asm volatile(
        "mma.sync.aligned.m16n8k8.row.col.f32.tf32.tf32.f32 "
        "{%0,%1,%2,%3}, {%4,%5,%6,%7}, {%8,%9}, {%0,%1,%2,%3};"
        : "+f"(c[0]), "+f"(c[1]), "+f"(c[2]), "+f"(c[3])
        : "r"(a0), "r"(a1), "r"(a2), "r"(a3), "r"(b0), "r"(b1));
}

__device__ __forceinline__ void cp16(uint32_t smem_addr, const void* gmem) {
    asm volatile("cp.async.cg.shared.global [%0], [%1], 16;\n"
                 :: "r"(smem_addr), "l"(gmem));
}

// Issue cp.async gather of one chunk (up to 64 rows) into the given X buffer.
__device__ __forceinline__ void prefetch_chunk(uint32_t xs_base,
                                               const float4* __restrict__ x4,
                                               const int* __restrict__ list,
                                               int cb, int m) {
    const int nrows = min(M_CH, m - cb);
    const int nops  = nrows * (D_DIM / 4);   // 16B ops
    for (int i = threadIdx.x; i < nops; i += NTHREADS) {
        int row = i >> 6;          // 64 float4 per row
        int c4  = i & 63;
        int tok = list[cb + row];
        cp16(xs_base + (uint32_t)(row * XS_STRIDE + c4 * 4) * 4u,
             x4 + (size_t)tok * (D_DIM / 4) + c4);
    }
}

__global__ void __launch_bounds__(NTHREADS, 1)
moe_pixels_kernel(const float* __restrict__ x,
                  const float* __restrict__ W,
                  const float* __restrict__ bias,
                  const int* __restrict__ bidx,
                  float* __restrict__ out,
                  int n_tok) {
    extern __shared__ float sm[];
    float* Ws   = sm + WS_OFF;
    float* Bs   = sm + BIAS_OFF;
    int*   list = (int*)(sm + LIST_OFF);
    int*   cnt  = (int*)(sm + CNT_OFF);

    const int tid       = threadIdx.x;
    const int e         = blockIdx.y;
    const int tile_base = blockIdx.x * TILE_TOKENS;

    if (tid == 0) *cnt = 0;
    __syncthreads();

    // ---- load W[e] into padded smem (tf32-rounded, done once) -------------
    const float4* Wg = (const float4*)(W + (size_t)e * D_DIM * P_DIM);
    for (int i = tid; i < (D_DIM * P_DIM) / 4; i += NTHREADS) {
        int k  = i >> 4;   // 16 float4 per 64-wide row
        int c4 = i & 15;
        float4 v = Wg[i];
        v.x = tf32r(v.x); v.y = tf32r(v.y); v.z = tf32r(v.z); v.w = tf32r(v.w);
        *(float4*)(Ws + k * WS_STRIDE + c4 * 4) = v;
    }
    if (tid < P_DIM) Bs[tid] = bias[e * P_DIM + tid];

    // ---- compact matching token ids ---------------------------------------
    #pragma unroll
    for (int i = 0; i < TILE_TOKENS / NTHREADS; i++) {
        int pos = tile_base + tid + i * NTHREADS;
        if (pos < n_tok && bidx[pos] == e) {
            int p = atomicAdd(cnt, 1);
            list[p] = pos;
        }
    }
    __syncthreads();
    const int m = *cnt;
    const int nch = (m + M_CH - 1) / M_CH;
    if (nch == 0) return;

    const int warp = tid >> 5;
    const int lane = tid & 31;
    const int g    = lane >> 2;   // 0..7
    const int t    = lane & 3;    // 0..3
    const int wr   = warp >> 2;   // 0..3 : row group (16 rows each)
    const int wc   = warp & 3;    // 0..3 : col group (16 cols each)

    const float4* x4 = (const float4*)x;

    const uint32_t xs0 = (uint32_t)__cvta_generic_to_shared(sm + XS0_OFF);
    const uint32_t xs1 = (uint32_t)__cvta_generic_to_shared(sm + XS1_OFF);

    // prologue: prefetch chunk 0
    prefetch_chunk(xs0, x4, list, 0, m);
    asm volatile("cp.async.commit_group;\n");

    for (int c = 0; c < nch; c++) {
        const int cb = c * M_CH;
        // prefetch next chunk into the other buffer, then wait for current
        if (c + 1 < nch) {
            prefetch_chunk((c & 1) ? xs0 : xs1, x4, list, cb + M_CH, m);
            asm volatile("cp.async.commit_group;\n");
            asm volatile("cp.async.wait_group 1;\n");
        } else {
            asm volatile("cp.async.wait_group 0;\n");
        }
        __syncthreads();

        const float* Xc = sm + ((c & 1) ? XS1_OFF : XS0_OFF);

        // ---- 64x64x256 tf32 MMA, accumulators seeded with bias ------------
        float acc[2][4];
        #pragma unroll
        for (int nt = 0; nt < 2; nt++) {
            int col = wc * 16 + nt * 8 + 2 * t;
            acc[nt][0] = Bs[col];
            acc[nt][1] = Bs[col + 1];
            acc[nt][2] = acc[nt][0];
            acc[nt][3] = acc[nt][1];
        }

        const float* xa = Xc + (wr * 16 + g) * XS_STRIDE + t;
        #pragma unroll 4
        for (int kk = 0; kk < D_DIM / 8; kk++) {
            const int k0 = kk * 8;
            uint32_t a0 = __float_as_uint(tf32r(xa[k0]));
            uint32_t a1 = __float_as_uint(tf32r(xa[8 * XS_STRIDE + k0]));
            uint32_t a2 = __float_as_uint(tf32r(xa[k0 + 4]));
            uint32_t a3 = __float_as_uint(tf32r(xa[8 * XS_STRIDE + k0 + 4]));
            const float* wb = Ws + (k0 + t) * WS_STRIDE + wc * 16 + g;
            #pragma unroll
            for (int nt = 0; nt < 2; nt++) {
                uint32_t b0 = __float_as_uint(wb[nt * 8]);
                uint32_t b1 = __float_as_uint(wb[4 * WS_STRIDE + nt * 8]);
                mma8(acc[nt], a0, a1, a2, a3, b0, b1);
            }
        }

        // ---- scatter results ----------------------------------------------
        const int rr0  = cb + wr * 16 + g;
        const int rr1  = rr0 + 8;
        const int tok0 = (rr0 < m) ? list[rr0] : -1;
        const int tok1 = (rr1 < m) ? list[rr1] : -1;
        #pragma unroll
        for (int nt = 0; nt < 2; nt++) {
            int col = wc * 16 + nt * 8 + 2 * t;
            if (tok0 >= 0)
                *(float2*)(out + (size_t)tok0 * P_DIM + col) =
                    make_float2(acc[nt][0], acc[nt][1]);
            if (tok1 >= 0)
                *(float2*)(out + (size_t)tok1 * P_DIM + col) =
                    make_float2(acc[nt][2], acc[nt][3]);
        }
        __syncthreads();   // MMA reads done before next prefetch overwrites buf
    }
}

extern "C" void kernel_launch(void* const* d_in, const int* in_sizes, int n_in,
                              void* d_out, int out_size) {
    const float* x    = (const float*)d_in[0];   // [B*T, 256] f32
    const float* W    = (const float*)d_in[1];   // [16, 256, 64] f32
    const float* b    = (const float*)d_in[2];   // [16, 64] f32
    const int*   bidx = (const int*)d_in[3];     // [B*T] i32
    float*       out  = (float*)d_out;           // [B*T, 64] f32

    const int n_tok = in_sizes[3];

    cudaFuncSetAttribute(moe_pixels_kernel,
                         cudaFuncAttributeMaxDynamicSharedMemorySize, SMEM_BYTES);

    dim3 grid((n_tok + TILE_TOKENS - 1) / TILE_TOKENS, 16);
    moe_pixels_kernel<<<grid, NTHREADS, SMEM_BYTES>>>(x, W, b, bidx, out, n_tok);
}